// round 12
// baseline (speedup 1.0000x reference)
#include <cuda_runtime.h>
#include <cuda_bf16.h>
#include <cstdint>
#include <math.h>

typedef unsigned long long u64;

#define L_   256
#define B_   128
#define D_   256
#define H_   256
#define NCOL 2048            // 2 dirs * 4H packed gate columns
#define HALF 16777216        // L*B*2H  (cells block size; hiddens follow)

// rec smem layout (float offsets)
#define F_W      0           // Wp2: [128 kpair][64 cpair][2 k]        = 131072 B
#define F_SH2    32768       // sh2: [32 row][260] u64 dup-pairs       = 66560 B
#define F_G      49408       // gates: [32][132] fp32                  = 16896 B
#define F_OFF    53632       // round offsets: 258 int
#define F_LP     53890       // chunk worklist: 32 int
#define F_PAR2   53922       // chunk parents: 32 int
#define DYN_SMEM 215936

// ------------------------- __device__ scratch (no runtime alloc) -------------------------
__device__ float g_wx[(size_t)NCOL * D_];
__device__ float g_bias[NCOL];
__device__ float g_xi[(size_t)L_ * B_ * NCOL];
__device__ float g_acc_c[(size_t)B_ * 257 * H_];
__device__ float g_acc_h[(size_t)B_ * 257 * H_];
__device__ float g_td_h[(size_t)L_ * B_ * H_];
__device__ float g_td_c[(size_t)L_ * B_ * H_];
__device__ int   g_rankbuf[2 * 128 * 256];   // [dir][b][node] dependency rank
__device__ int   g_wl[16 * 4096];            // per-cluster worklist (bl<<8|node), rank-sorted
__device__ int   g_offs[16 * 258];           // per-cluster round offsets
__device__ int   g_nrounds[16];

// ------------------------- f32x2 packed-FMA helpers -------------------------
__device__ __forceinline__ void fma2(u64& c, u64 a, u64 b) {
    asm("fma.rn.f32x2 %0, %1, %2, %3;" : "=l"(c) : "l"(a), "l"(b), "l"(c));
}
__device__ __forceinline__ u64 pk2(float x) {
    u64 r; asm("mov.b64 %0, {%1, %1};" : "=l"(r) : "f"(x)); return r;
}
__device__ __forceinline__ float2 up2(u64 v) {
    float2 f; asm("mov.b64 {%0, %1}, %2;" : "=f"(f.x), "=f"(f.y) : "l"(v)); return f;
}
__device__ __forceinline__ float sigm(float x) { return 1.0f / (1.0f + __expf(-x)); }

// ------------------------- rank kernel: dependency depth per (dir, batch, node) -------------
__global__ void rank_kernel(const int* __restrict__ parents) {
    int tid = threadIdx.x;              // 0..255
    int dir = tid >> 7, b = tid & 127;
    int rr[256];
    if (dir) {                          // td: rank = depth from root
        rr[0] = 0;
        for (int i = 1; i < 256; i++) rr[i] = rr[parents[i * B_ + b]] + 1;
    } else {                            // dt: rank = height above leaves
        for (int i = 0; i < 256; i++) rr[i] = 0;
        for (int i = 255; i >= 1; i--) {
            int p = parents[i * B_ + b];
            int v = rr[i] + 1;
            if (rr[p] < v) rr[p] = v;
        }
    }
    for (int i = 0; i < 256; i++) g_rankbuf[(dir * 128 + b) * 256 + i] = rr[i];
}

// ------------------------- worklist kernel: counting sort by rank per cluster ---------------
__global__ void wlist_kernel() {
    __shared__ int cnt[258], pos[258];
    __shared__ int maxr;
    int cl = blockIdx.x;                // 16 clusters = dir*8 + bg
    int dir = cl >> 3, bg = cl & 7;
    int t = threadIdx.x;
    for (int i = t; i < 258; i += 256) cnt[i] = 0;
    if (t == 0) maxr = 0;
    __syncthreads();
    for (int idx = t; idx < 4096; idx += 256) {
        int bl = idx >> 8, n = idx & 255;
        int rk = g_rankbuf[(dir * 128 + bg * 16 + bl) * 256 + n];
        atomicAdd(&cnt[rk], 1);
        atomicMax(&maxr, rk);
    }
    __syncthreads();
    if (t == 0) {
        int acc = 0;
        for (int i = 0; i <= maxr + 1; i++) {
            pos[i] = acc;
            g_offs[cl * 258 + i] = acc;
            acc += cnt[i];
        }
        g_nrounds[cl] = maxr + 1;
    }
    __syncthreads();
    for (int idx = t; idx < 4096; idx += 256) {
        int bl = idx >> 8, n = idx & 255;
        int rk = g_rankbuf[(dir * 128 + bg * 16 + bl) * 256 + n];
        int p = atomicAdd(&pos[rk], 1);
        g_wl[cl * 4096 + p] = (bl << 8) | n;
    }
}

// ------------------------- pack x-weights + fused biases -------------------------
__global__ void pack_wx_kernel(const float* __restrict__ ioux_w, const float* __restrict__ ioux_b,
                               const float* __restrict__ iouh_b, const float* __restrict__ fx_w,
                               const float* __restrict__ fx_b, const float* __restrict__ fh_b,
                               int base) {
    int c = blockIdx.x;
    int k = threadIdx.x;
    const float* src = (c < 768) ? (ioux_w + (size_t)c * D_) : (fx_w + (size_t)(c - 768) * D_);
    g_wx[(size_t)(base + c) * D_ + k] = src[k];
    if (k == 0)
        g_bias[base + c] = (c < 768) ? (ioux_b[c] + iouh_b[c]) : (fx_b[c - 768] + fh_b[c - 768]);
}

// ------------------------- precompute GEMM (f32x2): g_xi = inputs @ g_wx^T + g_bias ----------
__global__ __launch_bounds__(256) void xgemm_kernel(const float* __restrict__ A) {
    __shared__ u64 As2[16][65];
    __shared__ float Bs[16][68];
    int mBase = blockIdx.x * 64;
    int nBase = blockIdx.y * 64;
    int t = threadIdx.x;
    int tx = t & 15, ty = t >> 4;
    int lm = t >> 2;
    int lk = (t & 3) * 4;
    u64 acc[4][2] = {};
    for (int kt = 0; kt < 256; kt += 16) {
        float4 av = *(const float4*)(A + (size_t)(mBase + lm) * D_ + kt + lk);
        float4 bv = *(const float4*)(g_wx + (size_t)(nBase + lm) * D_ + kt + lk);
        As2[lk + 0][lm] = pk2(av.x); As2[lk + 1][lm] = pk2(av.y);
        As2[lk + 2][lm] = pk2(av.z); As2[lk + 3][lm] = pk2(av.w);
        Bs[lk + 0][lm] = bv.x; Bs[lk + 1][lm] = bv.y; Bs[lk + 2][lm] = bv.z; Bs[lk + 3][lm] = bv.w;
        __syncthreads();
#pragma unroll
        for (int k = 0; k < 16; k++) {
            u64 a0 = As2[k][ty * 4 + 0];
            u64 a1 = As2[k][ty * 4 + 1];
            u64 a2 = As2[k][ty * 4 + 2];
            u64 a3 = As2[k][ty * 4 + 3];
            ulonglong2 wv = *(const ulonglong2*)(&Bs[k][tx * 4]);
            fma2(acc[0][0], a0, wv.x); fma2(acc[0][1], a0, wv.y);
            fma2(acc[1][0], a1, wv.x); fma2(acc[1][1], a1, wv.y);
            fma2(acc[2][0], a2, wv.x); fma2(acc[2][1], a2, wv.y);
            fma2(acc[3][0], a3, wv.x); fma2(acc[3][1], a3, wv.y);
        }
        __syncthreads();
    }
    float4 bias = *(const float4*)(g_bias + nBase + tx * 4);
#pragma unroll
    for (int i = 0; i < 4; i++) {
        float2 lo = up2(acc[i][0]);
        float2 hi = up2(acc[i][1]);
        float4 o;
        o.x = lo.x + bias.x;
        o.y = lo.y + bias.y;
        o.z = hi.x + bias.z;
        o.w = hi.y + bias.w;
        *(float4*)(g_xi + (size_t)(mBase + ty * 4 + i) * NCOL + nBase + tx * 4) = o;
    }
}

// ------------------------- recurrent kernel: depth-parallel rounds, 32-row chunks -----------
// 128 CTAs = 16 clusters of 8. cluster = (dir, batch group of 16); rank r owns 32 h-dims
// (128 gate cols), Wh slice smem-resident. Chunks of 32 independent (b,node) rows; one
// cluster barrier per ROUND publishes h/c to peer ranks via L2.
__global__ __launch_bounds__(512, 1) __cluster_dims__(8, 1, 1)
void rec_kernel(const int* __restrict__ parents,
                const float* __restrict__ dt_iouh_w, const float* __restrict__ dt_fh_w,
                const float* __restrict__ td_iouh_w, const float* __restrict__ td_fh_w,
                float* __restrict__ out) {
    extern __shared__ float smem[];
    float* Wf      = smem + F_W;
    u64*   Wp2     = (u64*)(smem + F_W);
    u64*   sh2     = (u64*)(smem + F_SH2);     // [32 row][260] u64 dup-pairs
    float* gates_s = smem + F_G;               // [32][132]
    int*   off_s   = (int*)(smem + F_OFF);
    int*   lp_s    = (int*)(smem + F_LP);      // 32 pairs of this chunk
    int*   pp_s    = (int*)(smem + F_PAR2);    // 32 parents of this chunk

    const int blk = blockIdx.x;
    const int r   = blk & 7;
    const int cid = blk >> 3;
    const int dir = cid >> 3;
    const int bg  = cid & 7;
    const int t   = threadIdx.x;
    const int lane = t & 31;
    const int wid  = t >> 5;

    const float* iouh = dir ? td_iouh_w : dt_iouh_w;
    const float* fh   = dir ? td_fh_w : dt_fh_w;

    // ---- one-time: Wh slice -> k-pair/col-pair smem layout ----
    {
        int cc = t & 127;
        int g = cc >> 5, j = cc & 31;
        const float* src = (g < 3) ? (iouh + (size_t)(g * 256 + r * 32 + j) * H_)
                                   : (fh + (size_t)(r * 32 + j) * H_);
        int k0 = (t >> 7) * 64;
        for (int k = k0; k < k0 + 64; k++) {
            int idx = ((((k >> 1) * 64) + (cc >> 1)) * 2 + (k & 1)) * 2 + (cc & 1);
            Wf[idx] = src[k];
        }
    }
    for (int i = t; i < 258; i += 512) off_s[i] = g_offs[cid * 258 + i];
    const int nR = g_nrounds[cid];
    __syncthreads();

    // GEMM mapping: warp = cg (8 col-groups of 16 cols) x rh (2 row halves);
    // thread = col-pair (lane&7) x 4 rows (rh*16 + 4j + bq), bq = lane>>3
    const int cg  = wid & 7;
    const int rh  = wid >> 3;
    const int cp  = lane & 7;
    const int bq  = lane >> 3;
    const int cpg = cg * 8 + cp;
    // epilogue mapping: erow = t>>4 (32 rows), ejj = (t&15)*2 (2 gate dims)
    const int erow = t >> 4;
    const int ejj  = (t & 15) * 2;
    // gather mapping: warp wid handles rows wid and wid+16

    for (int rd = 0; rd < nR; rd++) {
        const int base = off_s[rd];
        const int end  = off_s[rd + 1];
        const int C = (end - base + 31) >> 5;

        for (int c = 0; c < C; c++) {
            // ---- stage: chunk worklist + parents (32 threads) ----
            if (t < 32) {
                int ridx = base + c * 32 + t;
                int pair = (ridx < end) ? __ldg(&g_wl[cid * 4096 + ridx]) : -1;
                lp_s[t] = pair;
                pp_s[t] = (pair >= 0) ? __ldg(&parents[(pair & 255) * B_ + bg * 16 + (pair >> 8)]) : 0;
            }
            __syncthreads();   // #0: lp/pp visible

            // ---- gather h rows into sh2 (warp -> rows wid, wid+16); xi/sc into regs ----
#pragma unroll
            for (int q = 0; q < 2; q++) {
                int row = wid + q * 16;
                int pair = lp_s[row];
                float4 h0 = make_float4(0.f, 0.f, 0.f, 0.f), h1 = h0;
                if (pair >= 0) {
                    int bl = pair >> 8, n = pair & 255;
                    int b = bg * 16 + bl;
                    int p = pp_s[row];
                    const float* hsrc;
                    bool zero = false;
                    if (dir) {
                        zero = (p == 256);
                        hsrc = g_td_h + ((size_t)p * B_ + b) * 256;
                    } else {
                        hsrc = g_acc_h + ((size_t)b * 257 + n) * 256;
                    }
                    if (!zero) {
                        h0 = __ldcg((const float4*)(hsrc + lane * 4));
                        h1 = __ldcg((const float4*)(hsrc + 128 + lane * 4));
                    }
                }
                *(ulonglong2*)(sh2 + row * 260 + lane * 4)           = make_ulonglong2(pk2(h0.x), pk2(h0.y));
                *(ulonglong2*)(sh2 + row * 260 + lane * 4 + 2)       = make_ulonglong2(pk2(h0.z), pk2(h0.w));
                *(ulonglong2*)(sh2 + row * 260 + 128 + lane * 4)     = make_ulonglong2(pk2(h1.x), pk2(h1.y));
                *(ulonglong2*)(sh2 + row * 260 + 128 + lane * 4 + 2) = make_ulonglong2(pk2(h1.z), pk2(h1.w));
            }
            // epilogue operands into registers (xi 4 gate pairs + sc pair)
            float2 exi0 = make_float2(0.f, 0.f), exi1 = exi0, exi2 = exi0, exi3 = exi0, esc = exi0;
            {
                int pair = lp_s[erow];
                if (pair >= 0) {
                    int bl = pair >> 8, n = pair & 255;
                    int b = bg * 16 + bl;
                    int p = pp_s[erow];
                    const float* xb = g_xi + ((size_t)n * B_ + b) * NCOL + dir * 1024 + r * 32 + ejj;
                    exi0 = __ldcg((const float2*)(xb));
                    exi1 = __ldcg((const float2*)(xb + 256));
                    exi2 = __ldcg((const float2*)(xb + 512));
                    exi3 = __ldcg((const float2*)(xb + 768));
                    if (dir) {
                        if (p != 256)
                            esc = __ldcg((const float2*)(g_td_c + ((size_t)p * B_ + b) * 256 + r * 32 + ejj));
                    } else {
                        esc = __ldcg((const float2*)(g_acc_c + ((size_t)b * 257 + n) * 256 + r * 32 + ejj));
                    }
                }
            }
            __syncthreads();   // #1: sh2 staged

            // ---- GEMM: gates[row][cols] = sum_k h[row][k] * W[col][k] (full K) ----
            {
                u64 a0 = 0, a1 = 0, a2 = 0, a3 = 0;
                const u64* hb = sh2 + (rh * 16 + bq) * 260;
                const u64* wb = Wp2 + (size_t)cpg * 2;
#pragma unroll 8
                for (int kp = 0; kp < 128; kp++) {
                    ulonglong2 wv = *(const ulonglong2*)(wb + kp * 128);
                    ulonglong2 h0 = *(const ulonglong2*)(hb + kp * 2);
                    ulonglong2 h1 = *(const ulonglong2*)(hb + 4 * 260 + kp * 2);
                    ulonglong2 h2 = *(const ulonglong2*)(hb + 8 * 260 + kp * 2);
                    ulonglong2 h3 = *(const ulonglong2*)(hb + 12 * 260 + kp * 2);
                    fma2(a0, h0.x, wv.x); fma2(a0, h0.y, wv.y);
                    fma2(a1, h1.x, wv.x); fma2(a1, h1.y, wv.y);
                    fma2(a2, h2.x, wv.x); fma2(a2, h2.y, wv.y);
                    fma2(a3, h3.x, wv.x); fma2(a3, h3.y, wv.y);
                }
                int gcol = cg * 16 + cp * 2;
                int rbase = rh * 16 + bq;
                *(u64*)(gates_s + (rbase + 0)  * 132 + gcol) = a0;
                *(u64*)(gates_s + (rbase + 4)  * 132 + gcol) = a1;
                *(u64*)(gates_s + (rbase + 8)  * 132 + gcol) = a2;
                *(u64*)(gates_s + (rbase + 12) * 132 + gcol) = a3;
            }
            __syncthreads();   // #2: gates ready

            // ---- epilogue: +xi, nonlinearities, state update, scatter (2 dims/thread) ----
            {
                int pair = lp_s[erow];
                if (pair >= 0) {
                    int bl = pair >> 8, n = pair & 255;
                    int b = bg * 16 + bl;
                    int p = pp_s[erow];
                    float2 gi = *(const float2*)(gates_s + erow * 132 + ejj);
                    float2 go = *(const float2*)(gates_s + erow * 132 + 32 + ejj);
                    float2 gu = *(const float2*)(gates_s + erow * 132 + 64 + ejj);
                    float2 gf = *(const float2*)(gates_s + erow * 132 + 96 + ejj);
                    float cc0, cc1, hh0, hh1;
                    {
                        float ig = sigm(gi.x + exi0.x);
                        float og = sigm(go.x + exi1.x);
                        float ug = tanhf(gu.x + exi2.x);
                        float fg = sigm(gf.x + exi3.x);
                        cc0 = ig * ug + fg * esc.x;
                        hh0 = og * tanhf(cc0);
                    }
                    {
                        float ig = sigm(gi.y + exi0.y);
                        float og = sigm(go.y + exi1.y);
                        float ug = tanhf(gu.y + exi2.y);
                        float fg = sigm(gf.y + exi3.y);
                        cc1 = ig * ug + fg * esc.y;
                        hh1 = og * tanhf(cc1);
                    }
                    size_t orow = ((size_t)n * B_ + b) * 512 + (size_t)dir * 256 + r * 32 + ejj;
                    __stcg((float2*)(out + orow), make_float2(cc0, cc1));
                    __stcg((float2*)(out + HALF + orow), make_float2(hh0, hh1));
                    if (dir) {
                        size_t trow = ((size_t)n * B_ + b) * 256 + r * 32 + ejj;
                        __stcg((float2*)(g_td_h + trow), make_float2(hh0, hh1));
                        __stcg((float2*)(g_td_c + trow), make_float2(cc0, cc1));
                    } else {
                        size_t arow = ((size_t)b * 257 + p) * 256 + r * 32 + ejj;
                        atomicAdd(&g_acc_h[arow], hh0);
                        atomicAdd(&g_acc_h[arow + 1], hh1);
                        atomicAdd(&g_acc_c[arow], cc0);
                        atomicAdd(&g_acc_c[arow + 1], cc1);
                    }
                }
            }
            __syncthreads();   // #3: chunk complete
        }

        // ---- publish this round's writes to peer ranks (release/acquire) ----
        asm volatile("barrier.cluster.arrive.aligned;" ::: "memory");
        asm volatile("barrier.cluster.wait.aligned;" ::: "memory");
    }
}

// ------------------------- launch -------------------------
extern "C" void kernel_launch(void* const* d_in, const int* in_sizes, int n_in,
                              void* d_out, int out_size) {
    const float* inputs = (const float*)d_in[0];
    const int* parents = (const int*)d_in[2];

    // dependency ranks + per-cluster rank-sorted worklists
    rank_kernel<<<1, 256>>>(parents);
    wlist_kernel<<<16, 256>>>();

    // pack x-side weights + fused biases (dt -> cols [0,1024), td -> [1024,2048))
    pack_wx_kernel<<<1024, 256>>>((const float*)d_in[3], (const float*)d_in[4],
                                  (const float*)d_in[6], (const float*)d_in[7],
                                  (const float*)d_in[8], (const float*)d_in[10], 0);
    pack_wx_kernel<<<1024, 256>>>((const float*)d_in[11], (const float*)d_in[12],
                                  (const float*)d_in[14], (const float*)d_in[15],
                                  (const float*)d_in[16], (const float*)d_in[18], 1024);

    // precompute x projections for all nodes/batches/dirs
    dim3 gg(512, 32);
    xgemm_kernel<<<gg, 256>>>(inputs);

    // zero dt accumulators (scan state) every launch
    void* accc = nullptr; void* acch = nullptr;
    cudaGetSymbolAddress(&accc, g_acc_c);
    cudaGetSymbolAddress(&acch, g_acc_h);
    cudaMemsetAsync(accc, 0, sizeof(float) * (size_t)B_ * 257 * H_);
    cudaMemsetAsync(acch, 0, sizeof(float) * (size_t)B_ * 257 * H_);

    // recurrent rounds: 16 clusters x 8 CTAs, 512 threads, 32-row chunks
    cudaFuncSetAttribute(rec_kernel, cudaFuncAttributeMaxDynamicSharedMemorySize, DYN_SMEM);
    rec_kernel<<<128, 512, DYN_SMEM>>>(parents,
                                       (const float*)d_in[5], (const float*)d_in[9],
                                       (const float*)d_in[13], (const float*)d_in[17],
                                       (float*)d_out);
}

// round 13
// speedup vs baseline: 1.0713x; 1.0713x over previous
#include <cuda_runtime.h>
#include <cuda_bf16.h>
#include <cstdint>
#include <math.h>

typedef unsigned long long u64;

#define L_   256
#define B_   128
#define D_   256
#define H_   256
#define NCOL 2048            // 2 dirs * 4H packed gate columns
#define HALF 16777216        // L*B*2H  (cells block size; hiddens follow)

// rec smem layout (float offsets)
#define F_W      0           // Wp2: [128 kpair][64 cpair][2 k]        = 131072 B
#define F_SH2    32768       // sh2: [32 row][260] u64 dup-pairs       = 66560 B
#define F_G      49408       // gates: [32][132] fp32                  = 16896 B
#define F_OFF    53632       // round offsets: 258 int
#define F_LP     53890       // chunk worklist: 32 int (8 per warpgroup)
#define F_PAR2   53922       // chunk parents: 32 int
#define DYN_SMEM 215936

// ------------------------- __device__ scratch (no runtime alloc) -------------------------
__device__ float g_wx[(size_t)NCOL * D_];
__device__ float g_bias[NCOL];
__device__ float g_xi[(size_t)L_ * B_ * NCOL];
__device__ float g_acc_c[(size_t)B_ * 257 * H_];
__device__ float g_acc_h[(size_t)B_ * 257 * H_];
__device__ float g_td_h[(size_t)L_ * B_ * H_];
__device__ float g_td_c[(size_t)L_ * B_ * H_];
__device__ int   g_rankbuf[2 * 128 * 256];   // [dir][b][node] dependency rank
__device__ int   g_wl[16 * 4096];            // per-cluster worklist (bl<<8|node), rank-sorted
__device__ int   g_offs[16 * 258];           // per-cluster round offsets
__device__ int   g_nrounds[16];

// ------------------------- helpers -------------------------
__device__ __forceinline__ void fma2(u64& c, u64 a, u64 b) {
    asm("fma.rn.f32x2 %0, %1, %2, %3;" : "=l"(c) : "l"(a), "l"(b), "l"(c));
}
__device__ __forceinline__ u64 pk2(float x) {
    u64 r; asm("mov.b64 %0, {%1, %1};" : "=l"(r) : "f"(x)); return r;
}
__device__ __forceinline__ float2 up2(u64 v) {
    float2 f; asm("mov.b64 {%0, %1}, %2;" : "=f"(f.x), "=f"(f.y) : "l"(v)); return f;
}
__device__ __forceinline__ float sigm(float x) { return 1.0f / (1.0f + __expf(-x)); }
__device__ __forceinline__ void wgbar(int wg) {
    asm volatile("bar.sync %0, 128;" :: "r"(wg + 1) : "memory");
}

// ------------------------- rank kernel: dependency depth per (dir, batch, node) -------------
__global__ void rank_kernel(const int* __restrict__ parents) {
    int tid = threadIdx.x;              // 0..255
    int dir = tid >> 7, b = tid & 127;
    int rr[256];
    if (dir) {                          // td: rank = depth from root
        rr[0] = 0;
        for (int i = 1; i < 256; i++) rr[i] = rr[parents[i * B_ + b]] + 1;
    } else {                            // dt: rank = height above leaves
        for (int i = 0; i < 256; i++) rr[i] = 0;
        for (int i = 255; i >= 1; i--) {
            int p = parents[i * B_ + b];
            int v = rr[i] + 1;
            if (rr[p] < v) rr[p] = v;
        }
    }
    for (int i = 0; i < 256; i++) g_rankbuf[(dir * 128 + b) * 256 + i] = rr[i];
}

// ------------------------- worklist kernel: counting sort by rank per cluster ---------------
__global__ void wlist_kernel() {
    __shared__ int cnt[258], pos[258];
    __shared__ int maxr;
    int cl = blockIdx.x;                // 16 clusters = dir*8 + bg
    int dir = cl >> 3, bg = cl & 7;
    int t = threadIdx.x;
    for (int i = t; i < 258; i += 256) cnt[i] = 0;
    if (t == 0) maxr = 0;
    __syncthreads();
    for (int idx = t; idx < 4096; idx += 256) {
        int bl = idx >> 8, n = idx & 255;
        int rk = g_rankbuf[(dir * 128 + bg * 16 + bl) * 256 + n];
        atomicAdd(&cnt[rk], 1);
        atomicMax(&maxr, rk);
    }
    __syncthreads();
    if (t == 0) {
        int acc = 0;
        for (int i = 0; i <= maxr + 1; i++) {
            pos[i] = acc;
            g_offs[cl * 258 + i] = acc;
            acc += cnt[i];
        }
        g_nrounds[cl] = maxr + 1;
    }
    __syncthreads();
    for (int idx = t; idx < 4096; idx += 256) {
        int bl = idx >> 8, n = idx & 255;
        int rk = g_rankbuf[(dir * 128 + bg * 16 + bl) * 256 + n];
        int p = atomicAdd(&pos[rk], 1);
        g_wl[cl * 4096 + p] = (bl << 8) | n;
    }
}

// ------------------------- pack x-weights + fused biases -------------------------
__global__ void pack_wx_kernel(const float* __restrict__ ioux_w, const float* __restrict__ ioux_b,
                               const float* __restrict__ iouh_b, const float* __restrict__ fx_w,
                               const float* __restrict__ fx_b, const float* __restrict__ fh_b,
                               int base) {
    int c = blockIdx.x;
    int k = threadIdx.x;
    const float* src = (c < 768) ? (ioux_w + (size_t)c * D_) : (fx_w + (size_t)(c - 768) * D_);
    g_wx[(size_t)(base + c) * D_ + k] = src[k];
    if (k == 0)
        g_bias[base + c] = (c < 768) ? (ioux_b[c] + iouh_b[c]) : (fx_b[c - 768] + fh_b[c - 768]);
}

// ------------------------- precompute GEMM (f32x2): g_xi = inputs @ g_wx^T + g_bias ----------
__global__ __launch_bounds__(256) void xgemm_kernel(const float* __restrict__ A) {
    __shared__ u64 As2[16][65];
    __shared__ float Bs[16][68];
    int mBase = blockIdx.x * 64;
    int nBase = blockIdx.y * 64;
    int t = threadIdx.x;
    int tx = t & 15, ty = t >> 4;
    int lm = t >> 2;
    int lk = (t & 3) * 4;
    u64 acc[4][2] = {};
    for (int kt = 0; kt < 256; kt += 16) {
        float4 av = *(const float4*)(A + (size_t)(mBase + lm) * D_ + kt + lk);
        float4 bv = *(const float4*)(g_wx + (size_t)(nBase + lm) * D_ + kt + lk);
        As2[lk + 0][lm] = pk2(av.x); As2[lk + 1][lm] = pk2(av.y);
        As2[lk + 2][lm] = pk2(av.z); As2[lk + 3][lm] = pk2(av.w);
        Bs[lk + 0][lm] = bv.x; Bs[lk + 1][lm] = bv.y; Bs[lk + 2][lm] = bv.z; Bs[lk + 3][lm] = bv.w;
        __syncthreads();
#pragma unroll
        for (int k = 0; k < 16; k++) {
            u64 a0 = As2[k][ty * 4 + 0];
            u64 a1 = As2[k][ty * 4 + 1];
            u64 a2 = As2[k][ty * 4 + 2];
            u64 a3 = As2[k][ty * 4 + 3];
            ulonglong2 wv = *(const ulonglong2*)(&Bs[k][tx * 4]);
            fma2(acc[0][0], a0, wv.x); fma2(acc[0][1], a0, wv.y);
            fma2(acc[1][0], a1, wv.x); fma2(acc[1][1], a1, wv.y);
            fma2(acc[2][0], a2, wv.x); fma2(acc[2][1], a2, wv.y);
            fma2(acc[3][0], a3, wv.x); fma2(acc[3][1], a3, wv.y);
        }
        __syncthreads();
    }
    float4 bias = *(const float4*)(g_bias + nBase + tx * 4);
#pragma unroll
    for (int i = 0; i < 4; i++) {
        float2 lo = up2(acc[i][0]);
        float2 hi = up2(acc[i][1]);
        float4 o;
        o.x = lo.x + bias.x;
        o.y = lo.y + bias.y;
        o.z = hi.x + bias.z;
        o.w = hi.y + bias.w;
        *(float4*)(g_xi + (size_t)(mBase + ty * 4 + i) * NCOL + nBase + nBase * 0 + tx * 4) = o;
    }
}

// ------------------------- recurrent kernel: warpgroup-concurrent chunks --------------------
// 128 CTAs = 16 clusters of 8. cluster = (dir, batch group of 16); rank r owns 32 h-dims
// (128 gate cols), Wh slice smem-resident. Each of 4 WARPGROUPS (128 thr) owns complete
// 8-row chunks end-to-end, synced by a private named barrier -> 4 chunks in flight per CTA
// (gather latency of one overlaps GEMM/epilogue of others). One block sync + one cluster
// release/acquire barrier per depth ROUND publishes h/c to peer ranks via L2.
__global__ __launch_bounds__(512, 1) __cluster_dims__(8, 1, 1)
void rec_kernel(const int* __restrict__ parents,
                const float* __restrict__ dt_iouh_w, const float* __restrict__ dt_fh_w,
                const float* __restrict__ td_iouh_w, const float* __restrict__ td_fh_w,
                float* __restrict__ out) {
    extern __shared__ float smem[];
    float* Wf      = smem + F_W;
    u64*   Wp2     = (u64*)(smem + F_W);
    u64*   sh2     = (u64*)(smem + F_SH2);     // [32 row][260] u64 dup-pairs
    float* gates_s = smem + F_G;               // [32][132]
    int*   off_s   = (int*)(smem + F_OFF);
    int*   lp_s    = (int*)(smem + F_LP);      // [4 wg][8]
    int*   pp_s    = (int*)(smem + F_PAR2);    // [4 wg][8]

    const int blk = blockIdx.x;
    const int r   = blk & 7;
    const int cid = blk >> 3;
    const int dir = cid >> 3;
    const int bg  = cid & 7;
    const int t   = threadIdx.x;
    const int lane = t & 31;
    const int wid  = t >> 5;
    const int wg   = wid >> 2;         // warpgroup 0..3
    const int w4   = wid & 3;          // warp within warpgroup
    const int t128 = t & 127;          // thread within warpgroup

    const float* iouh = dir ? td_iouh_w : dt_iouh_w;
    const float* fh   = dir ? td_fh_w : dt_fh_w;

    // ---- one-time: Wh slice -> k-pair/col-pair smem layout ----
    {
        int cc = t & 127;
        int g = cc >> 5, j = cc & 31;
        const float* src = (g < 3) ? (iouh + (size_t)(g * 256 + r * 32 + j) * H_)
                                   : (fh + (size_t)(r * 32 + j) * H_);
        int k0 = (t >> 7) * 64;
        for (int k = k0; k < k0 + 64; k++) {
            int idx = ((((k >> 1) * 64) + (cc >> 1)) * 2 + (k & 1)) * 2 + (cc & 1);
            Wf[idx] = src[k];
        }
    }
    for (int i = t; i < 258; i += 512) off_s[i] = g_offs[cid * 258 + i];
    const int nR = g_nrounds[cid];
    __syncthreads();

    // GEMM mapping (within warpgroup): thread = col-pair (2 cols) x 4 rows.
    const int cpg      = w4 * 16 + (lane & 15);    // 0..63 col pair -> cols (2cpg, 2cpg+1)
    const int rowhalf  = lane >> 4;                // rows rowhalf*4 .. +3 (local)
    const int grow0    = wg * 8 + rowhalf * 4;     // first global sh2/gates row
    // epilogue mapping: erow = wg*8 + (t128>>4), 2 gate dims per thread
    const int erow_l = t128 >> 4;                  // 0..7 local row
    const int erow   = wg * 8 + erow_l;
    const int ejj    = (t128 & 15) * 2;

    for (int rd = 0; rd < nR; rd++) {
        const int base = off_s[rd];
        const int end  = off_s[rd + 1];
        const int C8 = (end - base + 7) >> 3;

        for (int ci = wg; ci < C8; ci += 4) {
            // ---- stage: this warpgroup's 8-row chunk worklist + parents ----
            if (t128 < 8) {
                int ridx = base + ci * 8 + t128;
                int pair = (ridx < end) ? __ldg(&g_wl[cid * 4096 + ridx]) : -1;
                lp_s[wg * 8 + t128] = pair;
                pp_s[wg * 8 + t128] = (pair >= 0)
                    ? __ldg(&parents[(pair & 255) * B_ + bg * 16 + (pair >> 8)]) : 0;
            }
            wgbar(wg);   // #0: lp/pp visible

            // ---- gather h rows into sh2 (warp w4 -> local rows w4, w4+4) ----
#pragma unroll
            for (int q = 0; q < 2; q++) {
                int lr = w4 + q * 4;
                int row = wg * 8 + lr;
                int pair = lp_s[wg * 8 + lr];
                float4 h0 = make_float4(0.f, 0.f, 0.f, 0.f), h1 = h0;
                if (pair >= 0) {
                    int bl = pair >> 8, n = pair & 255;
                    int b = bg * 16 + bl;
                    int p = pp_s[wg * 8 + lr];
                    const float* hsrc;
                    bool zero = false;
                    if (dir) {
                        zero = (p == 256);
                        hsrc = g_td_h + ((size_t)p * B_ + b) * 256;
                    } else {
                        hsrc = g_acc_h + ((size_t)b * 257 + n) * 256;
                    }
                    if (!zero) {
                        h0 = __ldcg((const float4*)(hsrc + lane * 4));
                        h1 = __ldcg((const float4*)(hsrc + 128 + lane * 4));
                    }
                }
                *(ulonglong2*)(sh2 + row * 260 + lane * 4)           = make_ulonglong2(pk2(h0.x), pk2(h0.y));
                *(ulonglong2*)(sh2 + row * 260 + lane * 4 + 2)       = make_ulonglong2(pk2(h0.z), pk2(h0.w));
                *(ulonglong2*)(sh2 + row * 260 + 128 + lane * 4)     = make_ulonglong2(pk2(h1.x), pk2(h1.y));
                *(ulonglong2*)(sh2 + row * 260 + 128 + lane * 4 + 2) = make_ulonglong2(pk2(h1.z), pk2(h1.w));
            }
            // epilogue operands into registers (xi 4 gate pairs + sc pair)
            float2 exi0 = make_float2(0.f, 0.f), exi1 = exi0, exi2 = exi0, exi3 = exi0, esc = exi0;
            {
                int pair = lp_s[wg * 8 + erow_l];
                if (pair >= 0) {
                    int bl = pair >> 8, n = pair & 255;
                    int b = bg * 16 + bl;
                    int p = pp_s[wg * 8 + erow_l];
                    const float* xb = g_xi + ((size_t)n * B_ + b) * NCOL + dir * 1024 + r * 32 + ejj;
                    exi0 = __ldcg((const float2*)(xb));
                    exi1 = __ldcg((const float2*)(xb + 256));
                    exi2 = __ldcg((const float2*)(xb + 512));
                    exi3 = __ldcg((const float2*)(xb + 768));
                    if (dir) {
                        if (p != 256)
                            esc = __ldcg((const float2*)(g_td_c + ((size_t)p * B_ + b) * 256 + r * 32 + ejj));
                    } else {
                        esc = __ldcg((const float2*)(g_acc_c + ((size_t)b * 257 + n) * 256 + r * 32 + ejj));
                    }
                }
            }
            wgbar(wg);   // #1: sh2 staged

            // ---- GEMM: gates[rows][cols] = sum_k h[row][k] * W[col][k] (full K=256) ----
            {
                u64 a0 = 0, a1 = 0, a2 = 0, a3 = 0;
                const u64* hb = sh2 + grow0 * 260;
                const u64* wb = Wp2 + cpg * 2;
#pragma unroll 8
                for (int kp = 0; kp < 128; kp++) {
                    ulonglong2 wv = *(const ulonglong2*)(wb + kp * 128);
                    ulonglong2 h0 = *(const ulonglong2*)(hb + kp * 2);
                    ulonglong2 h1 = *(const ulonglong2*)(hb + 260 + kp * 2);
                    ulonglong2 h2 = *(const ulonglong2*)(hb + 520 + kp * 2);
                    ulonglong2 h3 = *(const ulonglong2*)(hb + 780 + kp * 2);
                    fma2(a0, h0.x, wv.x); fma2(a0, h0.y, wv.y);
                    fma2(a1, h1.x, wv.x); fma2(a1, h1.y, wv.y);
                    fma2(a2, h2.x, wv.x); fma2(a2, h2.y, wv.y);
                    fma2(a3, h3.x, wv.x); fma2(a3, h3.y, wv.y);
                }
                int gcol = cpg * 2;
                *(u64*)(gates_s + (grow0 + 0) * 132 + gcol) = a0;
                *(u64*)(gates_s + (grow0 + 1) * 132 + gcol) = a1;
                *(u64*)(gates_s + (grow0 + 2) * 132 + gcol) = a2;
                *(u64*)(gates_s + (grow0 + 3) * 132 + gcol) = a3;
            }
            wgbar(wg);   // #2: gates ready

            // ---- epilogue: +xi, nonlinearities, state update, scatter (2 dims/thread) ----
            {
                int pair = lp_s[wg * 8 + erow_l];
                if (pair >= 0) {
                    int bl = pair >> 8, n = pair & 255;
                    int b = bg * 16 + bl;
                    int p = pp_s[wg * 8 + erow_l];
                    float2 gi = *(const float2*)(gates_s + erow * 132 + ejj);
                    float2 go = *(const float2*)(gates_s + erow * 132 + 32 + ejj);
                    float2 gu = *(const float2*)(gates_s + erow * 132 + 64 + ejj);
                    float2 gf = *(const float2*)(gates_s + erow * 132 + 96 + ejj);
                    float cc0, cc1, hh0, hh1;
                    {
                        float ig = sigm(gi.x + exi0.x);
                        float og = sigm(go.x + exi1.x);
                        float ug = tanhf(gu.x + exi2.x);
                        float fg = sigm(gf.x + exi3.x);
                        cc0 = ig * ug + fg * esc.x;
                        hh0 = og * tanhf(cc0);
                    }
                    {
                        float ig = sigm(gi.y + exi0.y);
                        float og = sigm(go.y + exi1.y);
                        float ug = tanhf(gu.y + exi2.y);
                        float fg = sigm(gf.y + exi3.y);
                        cc1 = ig * ug + fg * esc.y;
                        hh1 = og * tanhf(cc1);
                    }
                    size_t orow = ((size_t)n * B_ + b) * 512 + (size_t)dir * 256 + r * 32 + ejj;
                    __stcg((float2*)(out + orow), make_float2(cc0, cc1));
                    __stcg((float2*)(out + HALF + orow), make_float2(hh0, hh1));
                    if (dir) {
                        size_t trow = ((size_t)n * B_ + b) * 256 + r * 32 + ejj;
                        __stcg((float2*)(g_td_h + trow), make_float2(hh0, hh1));
                        __stcg((float2*)(g_td_c + trow), make_float2(cc0, cc1));
                    } else {
                        size_t arow = ((size_t)b * 257 + p) * 256 + r * 32 + ejj;
                        atomicAdd(&g_acc_h[arow], hh0);
                        atomicAdd(&g_acc_h[arow + 1], hh1);
                        atomicAdd(&g_acc_c[arow], cc0);
                        atomicAdd(&g_acc_c[arow + 1], cc1);
                    }
                }
            }
            wgbar(wg);   // #3: chunk complete (lp/pp/sh2/gates reusable)
        }

        // ---- all warpgroups done: publish round's writes to peer ranks ----
        __syncthreads();
        asm volatile("barrier.cluster.arrive.aligned;" ::: "memory");
        asm volatile("barrier.cluster.wait.aligned;" ::: "memory");
    }
}

// ------------------------- launch -------------------------
extern "C" void kernel_launch(void* const* d_in, const int* in_sizes, int n_in,
                              void* d_out, int out_size) {
    const float* inputs = (const float*)d_in[0];
    const int* parents = (const int*)d_in[2];

    // dependency ranks + per-cluster rank-sorted worklists
    rank_kernel<<<1, 256>>>(parents);
    wlist_kernel<<<16, 256>>>();

    // pack x-side weights + fused biases (dt -> cols [0,1024), td -> [1024,2048))
    pack_wx_kernel<<<1024, 256>>>((const float*)d_in[3], (const float*)d_in[4],
                                  (const float*)d_in[6], (const float*)d_in[7],
                                  (const float*)d_in[8], (const float*)d_in[10], 0);
    pack_wx_kernel<<<1024, 256>>>((const float*)d_in[11], (const float*)d_in[12],
                                  (const float*)d_in[14], (const float*)d_in[15],
                                  (const float*)d_in[16], (const float*)d_in[18], 1024);

    // precompute x projections for all nodes/batches/dirs
    dim3 gg(512, 32);
    xgemm_kernel<<<gg, 256>>>(inputs);

    // zero dt accumulators (scan state) every launch
    void* accc = nullptr; void* acch = nullptr;
    cudaGetSymbolAddress(&accc, g_acc_c);
    cudaGetSymbolAddress(&acch, g_acc_h);
    cudaMemsetAsync(accc, 0, sizeof(float) * (size_t)B_ * 257 * H_);
    cudaMemsetAsync(acch, 0, sizeof(float) * (size_t)B_ * 257 * H_);

    // recurrent rounds: 16 clusters x 8 CTAs, 512 threads, 4 concurrent 8-row chunks/CTA
    cudaFuncSetAttribute(rec_kernel, cudaFuncAttributeMaxDynamicSharedMemorySize, DYN_SMEM);
    rec_kernel<<<128, 512, DYN_SMEM>>>(parents,
                                       (const float*)d_in[5], (const float*)d_in[9],
                                       (const float*)d_in[13], (const float*)d_in[17],
                                       (float*)d_out);
}

// round 14
// speedup vs baseline: 1.3340x; 1.2453x over previous
#include <cuda_runtime.h>
#include <cuda_bf16.h>
#include <cstdint>
#include <math.h>

typedef unsigned long long u64;

#define L_   256
#define B_   128
#define D_   256
#define H_   256
#define NCOL 2048            // 2 dirs * 4H packed gate columns
#define HALF 16777216        // L*B*2H  (cells block size; hiddens follow)

// rec smem layout (float offsets)
#define F_W      0           // Wr: [128 kp][2 g][32 cq][2] u64 k-pairs = 131072 B
#define F_H      32768       // h:  [2 wg][32 row][256] plain fp32      = 65536 B
#define F_G      49152       // gates: [2 wg][32][132] fp32             = 33792 B
#define F_OFF    57600       // round offsets: 258 int
#define F_LP     57858       // chunk worklist: [2 wg][32] int
#define F_PAR2   57922       // chunk parents:  [2 wg][32] int
#define DYN_SMEM 231944

// ------------------------- __device__ scratch (no runtime alloc) -------------------------
__device__ float g_wx[(size_t)NCOL * D_];
__device__ float g_bias[NCOL];
__device__ float g_xi[(size_t)L_ * B_ * NCOL];
__device__ float g_acc_c[(size_t)B_ * 257 * H_];
__device__ float g_acc_h[(size_t)B_ * 257 * H_];
__device__ float g_td_h[(size_t)L_ * B_ * H_];
__device__ float g_td_c[(size_t)L_ * B_ * H_];
__device__ int   g_rankbuf[2 * 128 * 256];
__device__ int   g_wl[16 * 4096];
__device__ int   g_offs[16 * 258];
__device__ int   g_nrounds[16];

// ------------------------- helpers -------------------------
__device__ __forceinline__ void fma2(u64& c, u64 a, u64 b) {
    asm("fma.rn.f32x2 %0, %1, %2, %3;" : "=l"(c) : "l"(a), "l"(b), "l"(c));
}
__device__ __forceinline__ u64 pk2(float x) {
    u64 r; asm("mov.b64 %0, {%1, %1};" : "=l"(r) : "f"(x)); return r;
}
__device__ __forceinline__ float2 up2(u64 v) {
    float2 f; asm("mov.b64 {%0, %1}, %2;" : "=f"(f.x), "=f"(f.y) : "l"(v)); return f;
}
__device__ __forceinline__ float sigm(float x) { return 1.0f / (1.0f + __expf(-x)); }
__device__ __forceinline__ void wgbar(int wg) {
    asm volatile("bar.sync %0, 256;" :: "r"(wg + 1) : "memory");
}

// ------------------------- rank kernel -------------------------
__global__ void rank_kernel(const int* __restrict__ parents) {
    int tid = threadIdx.x;
    int dir = tid >> 7, b = tid & 127;
    int rr[256];
    if (dir) {
        rr[0] = 0;
        for (int i = 1; i < 256; i++) rr[i] = rr[parents[i * B_ + b]] + 1;
    } else {
        for (int i = 0; i < 256; i++) rr[i] = 0;
        for (int i = 255; i >= 1; i--) {
            int p = parents[i * B_ + b];
            int v = rr[i] + 1;
            if (rr[p] < v) rr[p] = v;
        }
    }
    for (int i = 0; i < 256; i++) g_rankbuf[(dir * 128 + b) * 256 + i] = rr[i];
}

// ------------------------- worklist kernel -------------------------
__global__ void wlist_kernel() {
    __shared__ int cnt[258], pos[258];
    __shared__ int maxr;
    int cl = blockIdx.x;
    int dir = cl >> 3, bg = cl & 7;
    int t = threadIdx.x;
    for (int i = t; i < 258; i += 256) cnt[i] = 0;
    if (t == 0) maxr = 0;
    __syncthreads();
    for (int idx = t; idx < 4096; idx += 256) {
        int bl = idx >> 8, n = idx & 255;
        int rk = g_rankbuf[(dir * 128 + bg * 16 + bl) * 256 + n];
        atomicAdd(&cnt[rk], 1);
        atomicMax(&maxr, rk);
    }
    __syncthreads();
    if (t == 0) {
        int acc = 0;
        for (int i = 0; i <= maxr + 1; i++) {
            pos[i] = acc;
            g_offs[cl * 258 + i] = acc;
            acc += cnt[i];
        }
        g_nrounds[cl] = maxr + 1;
    }
    __syncthreads();
    for (int idx = t; idx < 4096; idx += 256) {
        int bl = idx >> 8, n = idx & 255;
        int rk = g_rankbuf[(dir * 128 + bg * 16 + bl) * 256 + n];
        int p = atomicAdd(&pos[rk], 1);
        g_wl[cl * 4096 + p] = (bl << 8) | n;
    }
}

// ------------------------- pack x-weights + fused biases -------------------------
__global__ void pack_wx_kernel(const float* __restrict__ ioux_w, const float* __restrict__ ioux_b,
                               const float* __restrict__ iouh_b, const float* __restrict__ fx_w,
                               const float* __restrict__ fx_b, const float* __restrict__ fh_b,
                               int base) {
    int c = blockIdx.x;
    int k = threadIdx.x;
    const float* src = (c < 768) ? (ioux_w + (size_t)c * D_) : (fx_w + (size_t)(c - 768) * D_);
    g_wx[(size_t)(base + c) * D_ + k] = src[k];
    if (k == 0)
        g_bias[base + c] = (c < 768) ? (ioux_b[c] + iouh_b[c]) : (fx_b[c - 768] + fh_b[c - 768]);
}

// ------------------------- precompute GEMM (f32x2) -------------------------
__global__ __launch_bounds__(256) void xgemm_kernel(const float* __restrict__ A) {
    __shared__ u64 As2[16][65];
    __shared__ float Bs[16][68];
    int mBase = blockIdx.x * 64;
    int nBase = blockIdx.y * 64;
    int t = threadIdx.x;
    int tx = t & 15, ty = t >> 4;
    int lm = t >> 2;
    int lk = (t & 3) * 4;
    u64 acc[4][2] = {};
    for (int kt = 0; kt < 256; kt += 16) {
        float4 av = *(const float4*)(A + (size_t)(mBase + lm) * D_ + kt + lk);
        float4 bv = *(const float4*)(g_wx + (size_t)(nBase + lm) * D_ + kt + lk);
        As2[lk + 0][lm] = pk2(av.x); As2[lk + 1][lm] = pk2(av.y);
        As2[lk + 2][lm] = pk2(av.z); As2[lk + 3][lm] = pk2(av.w);
        Bs[lk + 0][lm] = bv.x; Bs[lk + 1][lm] = bv.y; Bs[lk + 2][lm] = bv.z; Bs[lk + 3][lm] = bv.w;
        __syncthreads();
#pragma unroll
        for (int k = 0; k < 16; k++) {
            u64 a0 = As2[k][ty * 4 + 0];
            u64 a1 = As2[k][ty * 4 + 1];
            u64 a2 = As2[k][ty * 4 + 2];
            u64 a3 = As2[k][ty * 4 + 3];
            ulonglong2 wv = *(const ulonglong2*)(&Bs[k][tx * 4]);
            fma2(acc[0][0], a0, wv.x); fma2(acc[0][1], a0, wv.y);
            fma2(acc[1][0], a1, wv.x); fma2(acc[1][1], a1, wv.y);
            fma2(acc[2][0], a2, wv.x); fma2(acc[2][1], a2, wv.y);
            fma2(acc[3][0], a3, wv.x); fma2(acc[3][1], a3, wv.y);
        }
        __syncthreads();
    }
    float4 bias = *(const float4*)(g_bias + nBase + tx * 4);
#pragma unroll
    for (int i = 0; i < 4; i++) {
        float2 lo = up2(acc[i][0]);
        float2 hi = up2(acc[i][1]);
        float4 o;
        o.x = lo.x + bias.x;
        o.y = lo.y + bias.y;
        o.z = hi.x + bias.z;
        o.w = hi.y + bias.w;
        *(float4*)(g_xi + (size_t)(mBase + ty * 4 + i) * NCOL + nBase + tx * 4) = o;
    }
}

// ------------------------- recurrent kernel: k-lane f32x2, 2 warpgroups x 32-row chunks -----
// 128 CTAs = 16 clusters of 8. cluster = (dir, batch group of 16); rank r owns 32 h-dims
// (128 gate cols). W repacked once into k-pair u64s: u64 idx = kp*128 + g*64 + cq*2 + j
// holds W[col=4cq+2g+j][2kp..2kp+1]. Thread tile 4 rows x 4 cols, f32x2 lanes on K
// (accumulate even/odd k; horizontal add at end) -> 2.0 B/MAC lane-delivered, h un-duplicated.
__global__ __launch_bounds__(512, 1) __cluster_dims__(8, 1, 1)
void rec_kernel(const int* __restrict__ parents,
                const float* __restrict__ dt_iouh_w, const float* __restrict__ dt_fh_w,
                const float* __restrict__ td_iouh_w, const float* __restrict__ td_fh_w,
                float* __restrict__ out) {
    extern __shared__ float smem[];
    float* Wf      = smem + F_W;
    u64*   W64     = (u64*)(smem + F_W);
    float* h_s     = smem + F_H;               // [2][32][256]
    float* gates_s = smem + F_G;               // [2][32][132]
    int*   off_s   = (int*)(smem + F_OFF);
    int*   lp_s    = (int*)(smem + F_LP);      // [2][32]
    int*   pp_s    = (int*)(smem + F_PAR2);    // [2][32]

    const int blk = blockIdx.x;
    const int r   = blk & 7;
    const int cid = blk >> 3;
    const int dir = cid >> 3;
    const int bg  = cid & 7;
    const int t   = threadIdx.x;
    const int wg   = t >> 8;           // warpgroup 0..1 (256 threads each)
    const int t256 = t & 255;

    const float* iouh = dir ? td_iouh_w : dt_iouh_w;
    const float* fh   = dir ? td_fh_w : dt_fh_w;

    // ---- one-time: Wh slice -> k-pair u64 layout ----
    {
        int cc = t & 127;              // gate column 0..127
        int g = cc >> 5, j = cc & 31;
        const float* src = (g < 3) ? (iouh + (size_t)(g * 256 + r * 32 + j) * H_)
                                   : (fh + (size_t)(r * 32 + j) * H_);
        int gsel = (cc >> 1) & 1;
        int cq   = cc >> 2;
        int jj   = cc & 1;
        int k0 = (t >> 7) * 64;
        for (int k = k0; k < k0 + 64; k++) {
            int u64idx = (k >> 1) * 128 + gsel * 64 + cq * 2 + jj;
            Wf[u64idx * 2 + (k & 1)] = src[k];
        }
    }
    for (int i = t; i < 258; i += 512) off_s[i] = g_offs[cid * 258 + i];
    const int nR = g_nrounds[cid];
    __syncthreads();

    // GEMM mapping (within warpgroup): rg = rowgroup (4 rows), cq = colquad (4 cols)
    const int rg = t256 >> 5;          // 0..7
    const int cq = t256 & 31;          // 0..31
    // epilogue mapping: erow (32 rows), ejj = 4 h-dims (float4)
    const int erow = t256 >> 3;
    const int ejj  = (t256 & 7) * 4;
    // gather mapping: grow (32 rows), 8 float4 segments each
    const int grow = t256 >> 3;
    const int gseg = (t256 & 7) * 32;

    float* myh   = h_s + wg * 8192;
    float* myg   = gates_s + wg * 32 * 132;
    int*   mylp  = lp_s + wg * 32;
    int*   mypp  = pp_s + wg * 32;

    for (int rd = 0; rd < nR; rd++) {
        const int base = off_s[rd];
        const int end  = off_s[rd + 1];
        const int C32 = (end - base + 31) >> 5;

        for (int ci = wg; ci < C32; ci += 2) {
            // ---- stage: 32-row chunk worklist + parents ----
            if (t256 < 32) {
                int ridx = base + ci * 32 + t256;
                int pair = (ridx < end) ? __ldg(&g_wl[cid * 4096 + ridx]) : -1;
                mylp[t256] = pair;
                mypp[t256] = (pair >= 0)
                    ? __ldg(&parents[(pair & 255) * B_ + bg * 16 + (pair >> 8)]) : 0;
            }
            wgbar(wg);   // #0: lp/pp visible

            // ---- gather h rows (plain fp32) + epilogue operands into regs ----
            {
                int pair = mylp[grow];
                float4 z = make_float4(0.f, 0.f, 0.f, 0.f);
                const float* hsrc = nullptr;
                bool zero = true;
                if (pair >= 0) {
                    int bl = pair >> 8, n = pair & 255;
                    int b = bg * 16 + bl;
                    int p = mypp[grow];
                    if (dir) {
                        if (p != 256) { hsrc = g_td_h + ((size_t)p * B_ + b) * 256; zero = false; }
                    } else {
                        hsrc = g_acc_h + ((size_t)b * 257 + n) * 256; zero = false;
                    }
                }
#pragma unroll
                for (int q = 0; q < 8; q++) {
                    float4 v = zero ? z : __ldcg((const float4*)(hsrc + gseg + q * 4));
                    *(float4*)(myh + grow * 256 + gseg + q * 4) = v;
                }
            }
            float4 exi0, exi1, exi2, exi3, esc;
            exi0 = exi1 = exi2 = exi3 = esc = make_float4(0.f, 0.f, 0.f, 0.f);
            {
                int pair = mylp[erow];
                if (pair >= 0) {
                    int bl = pair >> 8, n = pair & 255;
                    int b = bg * 16 + bl;
                    int p = mypp[erow];
                    const float* xb = g_xi + ((size_t)n * B_ + b) * NCOL + dir * 1024 + r * 32 + ejj;
                    exi0 = __ldcg((const float4*)(xb));
                    exi1 = __ldcg((const float4*)(xb + 256));
                    exi2 = __ldcg((const float4*)(xb + 512));
                    exi3 = __ldcg((const float4*)(xb + 768));
                    if (dir) {
                        if (p != 256)
                            esc = __ldcg((const float4*)(g_td_c + ((size_t)p * B_ + b) * 256 + r * 32 + ejj));
                    } else {
                        esc = __ldcg((const float4*)(g_acc_c + ((size_t)b * 257 + n) * 256 + r * 32 + ejj));
                    }
                }
            }
            wgbar(wg);   // #1: h staged

            // ---- GEMM: 4 rows x 4 cols per thread, f32x2 lanes on K ----
            {
                u64 acc[16];
#pragma unroll
                for (int i = 0; i < 16; i++) acc[i] = 0ull;
                const float* hrow = myh + rg * 4 * 256;
                const u64* wq = W64 + cq * 2;
#pragma unroll 4
                for (int kq = 0; kq < 64; kq++) {          // 4 k per iteration
                    ulonglong2 h0 = *(const ulonglong2*)(hrow + kq * 4);
                    ulonglong2 h1 = *(const ulonglong2*)(hrow + 256 + kq * 4);
                    ulonglong2 h2 = *(const ulonglong2*)(hrow + 512 + kq * 4);
                    ulonglong2 h3 = *(const ulonglong2*)(hrow + 768 + kq * 4);
                    const u64* wk = wq + kq * 256;         // kp = 2kq
                    ulonglong2 wa0 = *(const ulonglong2*)(wk);           // cols 4cq,4cq+1 @ kp
                    ulonglong2 wb0 = *(const ulonglong2*)(wk + 64);      // cols 4cq+2,+3 @ kp
                    ulonglong2 wa1 = *(const ulonglong2*)(wk + 128);     // @ kp+1
                    ulonglong2 wb1 = *(const ulonglong2*)(wk + 192);
                    fma2(acc[0],  h0.x, wa0.x); fma2(acc[1],  h0.x, wa0.y);
                    fma2(acc[2],  h0.x, wb0.x); fma2(acc[3],  h0.x, wb0.y);
                    fma2(acc[4],  h1.x, wa0.x); fma2(acc[5],  h1.x, wa0.y);
                    fma2(acc[6],  h1.x, wb0.x); fma2(acc[7],  h1.x, wb0.y);
                    fma2(acc[8],  h2.x, wa0.x); fma2(acc[9],  h2.x, wa0.y);
                    fma2(acc[10], h2.x, wb0.x); fma2(acc[11], h2.x, wb0.y);
                    fma2(acc[12], h3.x, wa0.x); fma2(acc[13], h3.x, wa0.y);
                    fma2(acc[14], h3.x, wb0.x); fma2(acc[15], h3.x, wb0.y);
                    fma2(acc[0],  h0.y, wa1.x); fma2(acc[1],  h0.y, wa1.y);
                    fma2(acc[2],  h0.y, wb1.x); fma2(acc[3],  h0.y, wb1.y);
                    fma2(acc[4],  h1.y, wa1.x); fma2(acc[5],  h1.y, wa1.y);
                    fma2(acc[6],  h1.y, wb1.x); fma2(acc[7],  h1.y, wb1.y);
                    fma2(acc[8],  h2.y, wa1.x); fma2(acc[9],  h2.y, wa1.y);
                    fma2(acc[10], h2.y, wb1.x); fma2(acc[11], h2.y, wb1.y);
                    fma2(acc[12], h3.y, wa1.x); fma2(acc[13], h3.y, wa1.y);
                    fma2(acc[14], h3.y, wb1.x); fma2(acc[15], h3.y, wb1.y);
                }
                // horizontal add (even-k + odd-k) and store gate partials
#pragma unroll
                for (int i = 0; i < 4; i++) {
                    float2 c0 = up2(acc[i * 4 + 0]);
                    float2 c1 = up2(acc[i * 4 + 1]);
                    float2 c2 = up2(acc[i * 4 + 2]);
                    float2 c3 = up2(acc[i * 4 + 3]);
                    float4 o;
                    o.x = c0.x + c0.y;
                    o.y = c1.x + c1.y;
                    o.z = c2.x + c2.y;
                    o.w = c3.x + c3.y;
                    *(float4*)(myg + (rg * 4 + i) * 132 + cq * 4) = o;
                }
            }
            wgbar(wg);   // #2: gates ready

            // ---- epilogue: +xi, nonlinearities, state update, scatter (4 dims/thread) ----
            {
                int pair = mylp[erow];
                if (pair >= 0) {
                    int bl = pair >> 8, n = pair & 255;
                    int b = bg * 16 + bl;
                    int p = mypp[erow];
                    float4 gi = *(const float4*)(myg + erow * 132 + ejj);
                    float4 go = *(const float4*)(myg + erow * 132 + 32 + ejj);
                    float4 gu = *(const float4*)(myg + erow * 132 + 64 + ejj);
                    float4 gf = *(const float4*)(myg + erow * 132 + 96 + ejj);
                    float ii[4] = {gi.x + exi0.x, gi.y + exi0.y, gi.z + exi0.z, gi.w + exi0.w};
                    float oo[4] = {go.x + exi1.x, go.y + exi1.y, go.z + exi1.z, go.w + exi1.w};
                    float uu[4] = {gu.x + exi2.x, gu.y + exi2.y, gu.z + exi2.z, gu.w + exi2.w};
                    float ff[4] = {gf.x + exi3.x, gf.y + exi3.y, gf.z + exi3.z, gf.w + exi3.w};
                    float scv[4] = {esc.x, esc.y, esc.z, esc.w};
                    float cv[4], hv[4];
#pragma unroll
                    for (int d = 0; d < 4; d++) {
                        float ig = sigm(ii[d]);
                        float og = sigm(oo[d]);
                        float ug = tanhf(uu[d]);
                        float fg = sigm(ff[d]);
                        cv[d] = ig * ug + fg * scv[d];
                        hv[d] = og * tanhf(cv[d]);
                    }
                    float4 cf = make_float4(cv[0], cv[1], cv[2], cv[3]);
                    float4 hf = make_float4(hv[0], hv[1], hv[2], hv[3]);
                    size_t orow = ((size_t)n * B_ + b) * 512 + (size_t)dir * 256 + r * 32 + ejj;
                    __stcg((float4*)(out + orow), cf);
                    __stcg((float4*)(out + HALF + orow), hf);
                    if (dir) {
                        size_t trow = ((size_t)n * B_ + b) * 256 + r * 32 + ejj;
                        __stcg((float4*)(g_td_h + trow), hf);
                        __stcg((float4*)(g_td_c + trow), cf);
                    } else {
                        size_t arow = ((size_t)b * 257 + p) * 256 + r * 32 + ejj;
#pragma unroll
                        for (int d = 0; d < 4; d++) {
                            atomicAdd(&g_acc_h[arow + d], hv[d]);
                            atomicAdd(&g_acc_c[arow + d], cv[d]);
                        }
                    }
                }
            }
            wgbar(wg);   // #3: chunk complete
        }

        // ---- all warpgroups done: publish round's writes to peer ranks ----
        __syncthreads();
        asm volatile("barrier.cluster.arrive.aligned;" ::: "memory");
        asm volatile("barrier.cluster.wait.aligned;" ::: "memory");
    }
}

// ------------------------- launch -------------------------
extern "C" void kernel_launch(void* const* d_in, const int* in_sizes, int n_in,
                              void* d_out, int out_size) {
    const float* inputs = (const float*)d_in[0];
    const int* parents = (const int*)d_in[2];

    rank_kernel<<<1, 256>>>(parents);
    wlist_kernel<<<16, 256>>>();

    pack_wx_kernel<<<1024, 256>>>((const float*)d_in[3], (const float*)d_in[4],
                                  (const float*)d_in[6], (const float*)d_in[7],
                                  (const float*)d_in[8], (const float*)d_in[10], 0);
    pack_wx_kernel<<<1024, 256>>>((const float*)d_in[11], (const float*)d_in[12],
                                  (const float*)d_in[14], (const float*)d_in[15],
                                  (const float*)d_in[16], (const float*)d_in[18], 1024);

    dim3 gg(512, 32);
    xgemm_kernel<<<gg, 256>>>(inputs);

    void* accc = nullptr; void* acch = nullptr;
    cudaGetSymbolAddress(&accc, g_acc_c);
    cudaGetSymbolAddress(&acch, g_acc_h);
    cudaMemsetAsync(accc, 0, sizeof(float) * (size_t)B_ * 257 * H_);
    cudaMemsetAsync(acch, 0, sizeof(float) * (size_t)B_ * 257 * H_);

    cudaFuncSetAttribute(rec_kernel, cudaFuncAttributeMaxDynamicSharedMemorySize, DYN_SMEM);
    rec_kernel<<<128, 512, DYN_SMEM>>>(parents,
                                       (const float*)d_in[5], (const float*)d_in[9],
                                       (const float*)d_in[13], (const float*)d_in[17],
                                       (float*)d_out);
}

// round 15
// speedup vs baseline: 1.5155x; 1.1360x over previous
#include <cuda_runtime.h>
#include <cuda_bf16.h>
#include <cstdint>
#include <math.h>

typedef unsigned long long u64;

#define L_   256
#define B_   128
#define D_   256
#define H_   256
#define NCOL 2048            // 2 dirs * 4H packed gate columns
#define HALF 16777216        // L*B*2H  (cells block size; hiddens follow)

// rec smem layout (float offsets)
#define F_W      0           // W64: [128 kp][64 cpair][2 j] u64 k-pairs = 131072 B
#define F_H      32768       // h:  [2 wg][32 row][256] plain fp32        = 65536 B
#define F_G      49152       // gates: [2 wg][32][132] fp32               = 33792 B
#define F_OFF    57600       // round offsets: 258 int
#define F_LP     57858       // chunk worklist: [2 wg][32] int
#define F_PAR2   57922       // chunk parents:  [2 wg][32] int
#define DYN_SMEM 231944

// ------------------------- __device__ scratch (no runtime alloc) -------------------------
__device__ float g_wx[(size_t)NCOL * D_];
__device__ float g_bias[NCOL];
__device__ float g_xi[(size_t)L_ * B_ * NCOL];
__device__ float g_acc_c[(size_t)B_ * 257 * H_];
__device__ float g_acc_h[(size_t)B_ * 257 * H_];
__device__ float g_td_h[(size_t)L_ * B_ * H_];
__device__ float g_td_c[(size_t)L_ * B_ * H_];
__device__ int   g_rankbuf[2 * 128 * 256];
__device__ int   g_wl[16 * 4096];
__device__ int   g_offs[16 * 258];
__device__ int   g_nrounds[16];

// ------------------------- helpers -------------------------
__device__ __forceinline__ void fma2(u64& c, u64 a, u64 b) {
    asm("fma.rn.f32x2 %0, %1, %2, %3;" : "=l"(c) : "l"(a), "l"(b), "l"(c));
}
__device__ __forceinline__ float2 up2(u64 v) {
    float2 f; asm("mov.b64 {%0, %1}, %2;" : "=f"(f.x), "=f"(f.y) : "l"(v)); return f;
}
__device__ __forceinline__ float sigm(float x) { return 1.0f / (1.0f + __expf(-x)); }
__device__ __forceinline__ void wgbar(int wg) {
    asm volatile("bar.sync %0, 256;" :: "r"(wg + 1) : "memory");
}

// ------------------------- rank kernel -------------------------
__global__ void rank_kernel(const int* __restrict__ parents) {
    int tid = threadIdx.x;
    int dir = tid >> 7, b = tid & 127;
    int rr[256];
    if (dir) {
        rr[0] = 0;
        for (int i = 1; i < 256; i++) rr[i] = rr[parents[i * B_ + b]] + 1;
    } else {
        for (int i = 0; i < 256; i++) rr[i] = 0;
        for (int i = 255; i >= 1; i--) {
            int p = parents[i * B_ + b];
            int v = rr[i] + 1;
            if (rr[p] < v) rr[p] = v;
        }
    }
    for (int i = 0; i < 256; i++) g_rankbuf[(dir * 128 + b) * 256 + i] = rr[i];
}

// ------------------------- worklist kernel -------------------------
__global__ void wlist_kernel() {
    __shared__ int cnt[258], pos[258];
    __shared__ int maxr;
    int cl = blockIdx.x;
    int dir = cl >> 3, bg = cl & 7;
    int t = threadIdx.x;
    for (int i = t; i < 258; i += 256) cnt[i] = 0;
    if (t == 0) maxr = 0;
    __syncthreads();
    for (int idx = t; idx < 4096; idx += 256) {
        int bl = idx >> 8, n = idx & 255;
        int rk = g_rankbuf[(dir * 128 + bg * 16 + bl) * 256 + n];
        atomicAdd(&cnt[rk], 1);
        atomicMax(&maxr, rk);
    }
    __syncthreads();
    if (t == 0) {
        int acc = 0;
        for (int i = 0; i <= maxr + 1; i++) {
            pos[i] = acc;
            g_offs[cl * 258 + i] = acc;
            acc += cnt[i];
        }
        g_nrounds[cl] = maxr + 1;
    }
    __syncthreads();
    for (int idx = t; idx < 4096; idx += 256) {
        int bl = idx >> 8, n = idx & 255;
        int rk = g_rankbuf[(dir * 128 + bg * 16 + bl) * 256 + n];
        int p = atomicAdd(&pos[rk], 1);
        g_wl[cl * 4096 + p] = (bl << 8) | n;
    }
}

// ------------------------- pack x-weights + fused biases -------------------------
__global__ void pack_wx_kernel(const float* __restrict__ ioux_w, const float* __restrict__ ioux_b,
                               const float* __restrict__ iouh_b, const float* __restrict__ fx_w,
                               const float* __restrict__ fx_b, const float* __restrict__ fh_b,
                               int base) {
    int c = blockIdx.x;
    int k = threadIdx.x;
    const float* src = (c < 768) ? (ioux_w + (size_t)c * D_) : (fx_w + (size_t)(c - 768) * D_);
    g_wx[(size_t)(base + c) * D_ + k] = src[k];
    if (k == 0)
        g_bias[base + c] = (c < 768) ? (ioux_b[c] + iouh_b[c]) : (fx_b[c - 768] + fh_b[c - 768]);
}

// ------------------------- precompute GEMM: broadcast-A, k-lane f32x2 -------------------------
// 64x64 tile, 256 threads = 8 warps; warp w owns rows w*8..w*8+7 x all 64 cols;
// lane owns cols (2*lane, 2*lane+1). A plain fp32 (broadcast reads), W k-pair u64s.
__global__ __launch_bounds__(256) void xgemm_kernel(const float* __restrict__ A) {
    __shared__ float As[64 * 36];      // [row][k] stride 36
    __shared__ u64 Bs[16 * 64];        // [kp][cpair*2+j]
    float* Bsf = (float*)Bs;
    int mBase = blockIdx.x * 64;
    int nBase = blockIdx.y * 64;
    int t = threadIdx.x;
    int lane = t & 31;
    int w = t >> 5;
    int lm = t >> 2, lk = (t & 3) * 8;     // A stage: 4 thr per row
    int cn = t & 63, kr = (t >> 6) * 8;    // B stage: 4 thr per col

    u64 acc[16];
#pragma unroll
    for (int i = 0; i < 16; i++) acc[i] = 0ull;

    for (int kt = 0; kt < 256; kt += 32) {
        __syncthreads();
        // stage A tile [64 x 32] plain fp32
        {
            const float* ap = A + (size_t)(mBase + lm) * D_ + kt + lk;
            float4 a0 = *(const float4*)(ap);
            float4 a1 = *(const float4*)(ap + 4);
            *(float4*)(As + lm * 36 + lk) = a0;
            *(float4*)(As + lm * 36 + lk + 4) = a1;
        }
        // stage B tile [64 cols x 32 k] into k-pair u64 layout
        {
            const float* wp = g_wx + (size_t)(nBase + cn) * D_ + kt + kr;
            float4 b0 = *(const float4*)(wp);
            float4 b1 = *(const float4*)(wp + 4);
            float v[8] = {b0.x, b0.y, b0.z, b0.w, b1.x, b1.y, b1.z, b1.w};
#pragma unroll
            for (int k = 0; k < 8; k++) {
                int kk = kr + k;
                Bsf[((kk >> 1) * 64 + (cn >> 1) * 2 + (cn & 1)) * 2 + (kk & 1)] = v[k];
            }
        }
        __syncthreads();
        // GEMM over this k-tile: 8 kq iterations of 4k
        const float* hb = As + (w * 8) * 36;
        const u64* wb = Bs + lane * 2;
#pragma unroll
        for (int kq = 0; kq < 8; kq++) {
            ulonglong2 wv0 = *(const ulonglong2*)(wb + (2 * kq) * 64);
            ulonglong2 wv1 = *(const ulonglong2*)(wb + (2 * kq + 1) * 64);
#pragma unroll
            for (int rr = 0; rr < 8; rr++) {
                ulonglong2 hv = *(const ulonglong2*)(hb + rr * 36 + kq * 4);
                fma2(acc[rr * 2 + 0], hv.x, wv0.x);
                fma2(acc[rr * 2 + 1], hv.x, wv0.y);
                fma2(acc[rr * 2 + 0], hv.y, wv1.x);
                fma2(acc[rr * 2 + 1], hv.y, wv1.y);
            }
        }
    }
    // epilogue: horizontal add + bias, store
    float2 bias2 = *(const float2*)(g_bias + nBase + lane * 2);
#pragma unroll
    for (int rr = 0; rr < 8; rr++) {
        float2 e0 = up2(acc[rr * 2 + 0]);
        float2 e1 = up2(acc[rr * 2 + 1]);
        float2 o = make_float2(e0.x + e0.y + bias2.x, e1.x + e1.y + bias2.y);
        *(float2*)(g_xi + (size_t)(mBase + w * 8 + rr) * NCOL + nBase + lane * 2) = o;
    }
}

// ------------------------- recurrent kernel: broadcast-h 8x2 tiles, 2 wg x 32-row chunks ----
// 128 CTAs = 16 clusters of 8. cluster = (dir, batch group of 16); rank r owns 32 h-dims
// (128 gate cols). W in smem as k-pair u64s: idx = kp*128 + cp*2 + j -> W[col=2cp+j][2kp..2kp+1].
// Warp = 8 rows x 64 cols (broadcast h, 1 wf/load); lane = 8 rows x 2 cols (16 u64 acc).
// Crossbar = fma floor. Gather: one row per warp-instr, contiguous lanes (conflict-free).
__global__ __launch_bounds__(512, 1) __cluster_dims__(8, 1, 1)
void rec_kernel(const int* __restrict__ parents,
                const float* __restrict__ dt_iouh_w, const float* __restrict__ dt_fh_w,
                const float* __restrict__ td_iouh_w, const float* __restrict__ td_fh_w,
                float* __restrict__ out) {
    extern __shared__ float smem[];
    float* Wf      = smem + F_W;
    u64*   W64     = (u64*)(smem + F_W);
    float* h_s     = smem + F_H;               // [2][32][256]
    float* gates_s = smem + F_G;               // [2][32][132]
    int*   off_s   = (int*)(smem + F_OFF);
    int*   lp_s    = (int*)(smem + F_LP);      // [2][32]
    int*   pp_s    = (int*)(smem + F_PAR2);    // [2][32]

    const int blk = blockIdx.x;
    const int r   = blk & 7;
    const int cid = blk >> 3;
    const int dir = cid >> 3;
    const int bg  = cid & 7;
    const int t   = threadIdx.x;
    const int lane = t & 31;
    const int wg   = t >> 8;           // warpgroup 0..1
    const int t256 = t & 255;
    const int w8   = t256 >> 5;        // warp within warpgroup 0..7

    const float* iouh = dir ? td_iouh_w : dt_iouh_w;
    const float* fh   = dir ? td_fh_w : dt_fh_w;

    // ---- one-time: Wh slice -> k-pair/col-pair u64 layout ----
    {
        int cc = t & 127;              // gate column 0..127 (g*32+j)
        int g = cc >> 5, j = cc & 31;
        const float* src = (g < 3) ? (iouh + (size_t)(g * 256 + r * 32 + j) * H_)
                                   : (fh + (size_t)(r * 32 + j) * H_);
        int k0 = (t >> 7) * 64;
        for (int k = k0; k < k0 + 64; k++) {
            int u64idx = (k >> 1) * 128 + (cc >> 1) * 2 + (cc & 1);
            Wf[u64idx * 2 + (k & 1)] = src[k];
        }
    }
    for (int i = t; i < 258; i += 512) off_s[i] = g_offs[cid * 258 + i];
    const int nR = g_nrounds[cid];
    __syncthreads();

    // GEMM mapping: warp w8 -> rows (w8&3)*8..+7, col half (w8>>2)*64; lane -> 2 cols
    const int rowg  = (w8 & 3) * 8;
    const int chalf = w8 >> 2;
    const int cp    = chalf * 32 + lane;   // global col pair 0..63
    // epilogue mapping: erow (32 rows), ejj = 4 h-dims
    const int erow = t256 >> 3;
    const int ejj  = (t256 & 7) * 4;

    float* myh   = h_s + wg * 8192;
    float* myg   = gates_s + wg * 32 * 132;
    int*   mylp  = lp_s + wg * 32;
    int*   mypp  = pp_s + wg * 32;

    for (int rd = 0; rd < nR; rd++) {
        const int base = off_s[rd];
        const int end  = off_s[rd + 1];
        const int C32 = (end - base + 31) >> 5;

        for (int ci = wg; ci < C32; ci += 2) {
            // ---- stage: 32-row chunk worklist + parents ----
            if (t256 < 32) {
                int ridx = base + ci * 32 + t256;
                int pair = (ridx < end) ? __ldg(&g_wl[cid * 4096 + ridx]) : -1;
                mylp[t256] = pair;
                mypp[t256] = (pair >= 0)
                    ? __ldg(&parents[(pair & 255) * B_ + bg * 16 + (pair >> 8)]) : 0;
            }
            wgbar(wg);   // #0: lp/pp visible

            // ---- gather h: warp w8 -> rows w8*4..+3, lanes contiguous (conflict-free) ----
#pragma unroll
            for (int q = 0; q < 4; q++) {
                int row = w8 * 4 + q;
                int pair = mylp[row];
                float4 z = make_float4(0.f, 0.f, 0.f, 0.f);
                const float* hsrc = nullptr;
                bool zero = true;
                if (pair >= 0) {
                    int bl = pair >> 8, n = pair & 255;
                    int b = bg * 16 + bl;
                    int p = mypp[row];
                    if (dir) {
                        if (p != 256) { hsrc = g_td_h + ((size_t)p * B_ + b) * 256; zero = false; }
                    } else {
                        hsrc = g_acc_h + ((size_t)b * 257 + n) * 256; zero = false;
                    }
                }
                float4 v0 = zero ? z : __ldcg((const float4*)(hsrc + lane * 4));
                float4 v1 = zero ? z : __ldcg((const float4*)(hsrc + 128 + lane * 4));
                *(float4*)(myh + row * 256 + lane * 4) = v0;
                *(float4*)(myh + row * 256 + 128 + lane * 4) = v1;
            }
            // epilogue operands into regs
            float4 exi0, exi1, exi2, exi3, esc;
            exi0 = exi1 = exi2 = exi3 = esc = make_float4(0.f, 0.f, 0.f, 0.f);
            {
                int pair = mylp[erow];
                if (pair >= 0) {
                    int bl = pair >> 8, n = pair & 255;
                    int b = bg * 16 + bl;
                    int p = mypp[erow];
                    const float* xb = g_xi + ((size_t)n * B_ + b) * NCOL + dir * 1024 + r * 32 + ejj;
                    exi0 = __ldcg((const float4*)(xb));
                    exi1 = __ldcg((const float4*)(xb + 256));
                    exi2 = __ldcg((const float4*)(xb + 512));
                    exi3 = __ldcg((const float4*)(xb + 768));
                    if (dir) {
                        if (p != 256)
                            esc = __ldcg((const float4*)(g_td_c + ((size_t)p * B_ + b) * 256 + r * 32 + ejj));
                    } else {
                        esc = __ldcg((const float4*)(g_acc_c + ((size_t)b * 257 + n) * 256 + r * 32 + ejj));
                    }
                }
            }
            wgbar(wg);   // #1: h staged

            // ---- GEMM: 8 rows x 2 cols per lane, f32x2 on K, broadcast h ----
            {
                u64 acc[16];
#pragma unroll
                for (int i = 0; i < 16; i++) acc[i] = 0ull;
                const float* hb = myh + rowg * 256;
                const u64* wb = W64 + cp * 2;
#pragma unroll 4
                for (int kq = 0; kq < 64; kq++) {
                    ulonglong2 wv0 = *(const ulonglong2*)(wb + (2 * kq) * 128);
                    ulonglong2 wv1 = *(const ulonglong2*)(wb + (2 * kq + 1) * 128);
#pragma unroll
                    for (int rr = 0; rr < 8; rr++) {
                        ulonglong2 hv = *(const ulonglong2*)(hb + rr * 256 + kq * 4);
                        fma2(acc[rr * 2 + 0], hv.x, wv0.x);
                        fma2(acc[rr * 2 + 1], hv.x, wv0.y);
                        fma2(acc[rr * 2 + 0], hv.y, wv1.x);
                        fma2(acc[rr * 2 + 1], hv.y, wv1.y);
                    }
                }
                int gc = cp * 2;
#pragma unroll
                for (int rr = 0; rr < 8; rr++) {
                    float2 e0 = up2(acc[rr * 2 + 0]);
                    float2 e1 = up2(acc[rr * 2 + 1]);
                    *(float2*)(myg + (rowg + rr) * 132 + gc) =
                        make_float2(e0.x + e0.y, e1.x + e1.y);
                }
            }
            wgbar(wg);   // #2: gates ready

            // ---- epilogue: +xi, nonlinearities, state update, scatter (4 dims/thread) ----
            {
                int pair = mylp[erow];
                if (pair >= 0) {
                    int bl = pair >> 8, n = pair & 255;
                    int b = bg * 16 + bl;
                    int p = mypp[erow];
                    float4 gi = *(const float4*)(myg + erow * 132 + ejj);
                    float4 go = *(const float4*)(myg + erow * 132 + 32 + ejj);
                    float4 gu = *(const float4*)(myg + erow * 132 + 64 + ejj);
                    float4 gf = *(const float4*)(myg + erow * 132 + 96 + ejj);
                    float ii[4] = {gi.x + exi0.x, gi.y + exi0.y, gi.z + exi0.z, gi.w + exi0.w};
                    float oo[4] = {go.x + exi1.x, go.y + exi1.y, go.z + exi1.z, go.w + exi1.w};
                    float uu[4] = {gu.x + exi2.x, gu.y + exi2.y, gu.z + exi2.z, gu.w + exi2.w};
                    float ff[4] = {gf.x + exi3.x, gf.y + exi3.y, gf.z + exi3.z, gf.w + exi3.w};
                    float scv[4] = {esc.x, esc.y, esc.z, esc.w};
                    float cv[4], hv[4];
#pragma unroll
                    for (int d = 0; d < 4; d++) {
                        float ig = sigm(ii[d]);
                        float og = sigm(oo[d]);
                        float ug = tanhf(uu[d]);
                        float fg = sigm(ff[d]);
                        cv[d] = ig * ug + fg * scv[d];
                        hv[d] = og * tanhf(cv[d]);
                    }
                    float4 cf = make_float4(cv[0], cv[1], cv[2], cv[3]);
                    float4 hf = make_float4(hv[0], hv[1], hv[2], hv[3]);
                    size_t orow = ((size_t)n * B_ + b) * 512 + (size_t)dir * 256 + r * 32 + ejj;
                    __stcg((float4*)(out + orow), cf);
                    __stcg((float4*)(out + HALF + orow), hf);
                    if (dir) {
                        size_t trow = ((size_t)n * B_ + b) * 256 + r * 32 + ejj;
                        __stcg((float4*)(g_td_h + trow), hf);
                        __stcg((float4*)(g_td_c + trow), cf);
                    } else {
                        size_t arow = ((size_t)b * 257 + p) * 256 + r * 32 + ejj;
#pragma unroll
                        for (int d = 0; d < 4; d++) {
                            atomicAdd(&g_acc_h[arow + d], hv[d]);
                            atomicAdd(&g_acc_c[arow + d], cv[d]);
                        }
                    }
                }
            }
            wgbar(wg);   // #3: chunk complete
        }

        // ---- all warpgroups done: publish round's writes to peer ranks ----
        __syncthreads();
        asm volatile("barrier.cluster.arrive.aligned;" ::: "memory");
        asm volatile("barrier.cluster.wait.aligned;" ::: "memory");
    }
}

// ------------------------- launch -------------------------
extern "C" void kernel_launch(void* const* d_in, const int* in_sizes, int n_in,
                              void* d_out, int out_size) {
    const float* inputs = (const float*)d_in[0];
    const int* parents = (const int*)d_in[2];

    rank_kernel<<<1, 256>>>(parents);
    wlist_kernel<<<16, 256>>>();

    pack_wx_kernel<<<1024, 256>>>((const float*)d_in[3], (const float*)d_in[4],
                                  (const float*)d_in[6], (const float*)d_in[7],
                                  (const float*)d_in[8], (const float*)d_in[10], 0);
    pack_wx_kernel<<<1024, 256>>>((const float*)d_in[11], (const float*)d_in[12],
                                  (const float*)d_in[14], (const float*)d_in[15],
                                  (const float*)d_in[16], (const float*)d_in[18], 1024);

    dim3 gg(512, 32);
    xgemm_kernel<<<gg, 256>>>(inputs);

    void* accc = nullptr; void* acch = nullptr;
    cudaGetSymbolAddress(&accc, g_acc_c);
    cudaGetSymbolAddress(&acch, g_acc_h);
    cudaMemsetAsync(accc, 0, sizeof(float) * (size_t)B_ * 257 * H_);
    cudaMemsetAsync(acch, 0, sizeof(float) * (size_t)B_ * 257 * H_);

    cudaFuncSetAttribute(rec_kernel, cudaFuncAttributeMaxDynamicSharedMemorySize, DYN_SMEM);
    rec_kernel<<<128, 512, DYN_SMEM>>>(parents,
                                       (const float*)d_in[5], (const float*)d_in[9],
                                       (const float*)d_in[13], (const float*)d_in[17],
                                       (float*)d_out);
}